// round 16
// baseline (speedup 1.0000x reference)
#include <cuda_runtime.h>
#include <cuda_bf16.h>
#include <math.h>
#include <stdint.h>

#define B_  2
#define S_  2048
#define E_  1024
#define H_  16
#define D_  64
#define E3_ 3072
#define M_  (B_ * S_)   // 4096

// ---------------- device-global scratch (allocation-free rule) -------------
__device__ __nv_bfloat16 g_xh [(size_t)M_  * E_ ], g_xl [(size_t)M_  * E_ ];
__device__ __nv_bfloat16 g_wqh[(size_t)E3_ * E_ ], g_wql[(size_t)E3_ * E_ ];
__device__ __nv_bfloat16 g_owh[(size_t)E_  * E_ ], g_owl[(size_t)E_  * E_ ];
__device__ __nv_bfloat16 g_qkvh[(size_t)M_ * E3_], g_qkvl[(size_t)M_ * E3_];
__device__ __nv_bfloat16 g_ath[(size_t)M_  * E_ ], g_atl[(size_t)M_  * E_ ];

// ---------------- PTX helpers (baseline ISA only) --------------------------
__device__ __forceinline__ void mma16816(float* c, const uint32_t* a,
                                         const uint32_t* b) {
    asm volatile(
        "mma.sync.aligned.m16n8k16.row.col.f32.bf16.bf16.f32 "
        "{%0,%1,%2,%3}, {%4,%5,%6,%7}, {%8,%9}, {%0,%1,%2,%3};"
        : "+f"(c[0]), "+f"(c[1]), "+f"(c[2]), "+f"(c[3])
        : "r"(a[0]), "r"(a[1]), "r"(a[2]), "r"(a[3]), "r"(b[0]), "r"(b[1]));
}

__device__ __forceinline__ uint32_t pack_bf16(float a, float b) {
    __nv_bfloat162 h = __floats2bfloat162_rn(a, b);
    return *(uint32_t*)&h;
}

__device__ __forceinline__ uint32_t smem_u32(const void* p) {
    uint32_t a;
    asm("{ .reg .u64 t; cvta.to.shared.u64 t, %1; cvt.u32.u64 %0, t; }"
        : "=r"(a) : "l"(p));
    return a;
}

__device__ __forceinline__ void cp_async16(uint32_t dst, const void* src) {
    asm volatile("cp.async.ca.shared.global [%0], [%1], 16;"
                 :: "r"(dst), "l"(src));
}
#define CP_COMMIT() asm volatile("cp.async.commit_group;" ::: "memory")
#define CP_WAIT_0() asm volatile("cp.async.wait_group 0;" ::: "memory")

__device__ __forceinline__ void ldsm4(uint32_t* r, uint32_t addr) {
    asm volatile(
        "ldmatrix.sync.aligned.m8n8.x4.shared.b16 {%0,%1,%2,%3}, [%4];"
        : "=r"(r[0]), "=r"(r[1]), "=r"(r[2]), "=r"(r[3]) : "r"(addr));
}
__device__ __forceinline__ void ldsm4t(uint32_t* r, uint32_t addr) {
    asm volatile(
        "ldmatrix.sync.aligned.m8n8.x4.trans.shared.b16 {%0,%1,%2,%3}, [%4];"
        : "=r"(r[0]), "=r"(r[1]), "=r"(r[2]), "=r"(r[3]) : "r"(addr));
}

// ---------------- split fp32 -> bf16 hi/lo ---------------------------------
__global__ __launch_bounds__(256) void split_bf16(
    const float* __restrict__ src, __nv_bfloat16* __restrict__ hi,
    __nv_bfloat16* __restrict__ lo, int n4)
{
    const int i = blockIdx.x * 256 + threadIdx.x;
    if (i >= n4) return;
    float4 v = ((const float4*)src)[i];
    uint32_t h0 = pack_bf16(v.x, v.y);
    uint32_t h1 = pack_bf16(v.z, v.w);
    __nv_bfloat162 H0 = *(__nv_bfloat162*)&h0;
    __nv_bfloat162 H1 = *(__nv_bfloat162*)&h1;
    uint32_t l0 = pack_bf16(v.x - __bfloat162float(H0.x),
                            v.y - __bfloat162float(H0.y));
    uint32_t l1 = pack_bf16(v.z - __bfloat162float(H1.x),
                            v.w - __bfloat162float(H1.y));
    ((uint2*)hi)[i] = make_uint2(h0, h1);
    ((uint2*)lo)[i] = make_uint2(l0, l1);
}

// ===========================================================================
// Split-bf16 HMMA GEMM; 4 warps (2x2), 64x64 warp tiles, 2 CTA/SM.
// Single-barrier pipelined loop: wait -> sync -> stage next -> compute.
// ===========================================================================
#define GPAD 40
#define GARR (128 * GPAD)
#define GSTAGE (4 * GARR)
#define GEMM_SMEM (2 * GSTAGE * 2)

__global__ __launch_bounds__(128, 2) void gemm_tc(
    const __nv_bfloat16* __restrict__ Ahg, const __nv_bfloat16* __restrict__ Alg,
    const __nv_bfloat16* __restrict__ Bhg, const __nv_bfloat16* __restrict__ Blg,
    const float* __restrict__ bias,
    float* __restrict__ Cf, __nv_bfloat16* __restrict__ Ch,
    __nv_bfloat16* __restrict__ Cl,
    int M, int N, int K)
{
    extern __shared__ __nv_bfloat16 sm[];
    const uint32_t smb = smem_u32(sm);

    const int tid = threadIdx.x;
    const int wid = tid >> 5;
    const int lid = tid & 31;
    const int gq  = lid >> 2;
    const int qt  = lid & 3;
    const int m0 = blockIdx.y * 128;
    const int n0 = blockIdx.x * 128;
    const int warpM = (wid >> 1) * 64;
    const int warpN = (wid & 1) * 64;

    const int a_r = (lid & 7) + ((lid & 8)  ? 8 : 0);
    const int a_c = (lid & 16) ? 8 : 0;
    const int b_r = (lid & 7) + ((lid & 16) ? 8 : 0);
    const int b_c = (lid & 8) ? 8 : 0;

    float c[4][8][4];
    #pragma unroll
    for (int mt = 0; mt < 4; mt++)
        #pragma unroll
        for (int nt = 0; nt < 8; nt++)
            c[mt][nt][0] = c[mt][nt][1] = c[mt][nt][2] = c[mt][nt][3] = 0.f;

    int srow[4], sseg[4];
    #pragma unroll
    for (int i = 0; i < 4; i++) {
        const int idx = tid + i * 128;
        srow[i] = idx >> 2;
        sseg[i] = (idx & 3) * 8;
    }

    auto stage = [&](int s, int kb) {
        const uint32_t base = smb + (uint32_t)(s * GSTAGE) * 2;
        #pragma unroll
        for (int i = 0; i < 4; i++) {
            const int r = srow[i], g = sseg[i];
            cp_async16(base + (uint32_t)(0*GARR + r*GPAD + g)*2,
                       &Ahg[(size_t)(m0 + r) * K + kb + g]);
            cp_async16(base + (uint32_t)(1*GARR + r*GPAD + g)*2,
                       &Alg[(size_t)(m0 + r) * K + kb + g]);
            cp_async16(base + (uint32_t)(2*GARR + r*GPAD + g)*2,
                       &Bhg[(size_t)(n0 + r) * K + kb + g]);
            cp_async16(base + (uint32_t)(3*GARR + r*GPAD + g)*2,
                       &Blg[(size_t)(n0 + r) * K + kb + g]);
        }
    };

    stage(0, 0);
    CP_COMMIT();

    int s = 0;
    for (int kb = 0; kb < K; kb += 32) {
        CP_WAIT_0();          // chunk kb has landed (this thread's copies)
        __syncthreads();      // ...and everyone else's; prev compute done

        if (kb + 32 < K) { stage(s ^ 1, kb + 32); CP_COMMIT(); }

        const uint32_t Ahb = smb + (uint32_t)(s * GSTAGE          ) * 2;
        const uint32_t Alb = smb + (uint32_t)(s * GSTAGE + 1*GARR ) * 2;
        const uint32_t Bhb = smb + (uint32_t)(s * GSTAGE + 2*GARR ) * 2;
        const uint32_t Blb = smb + (uint32_t)(s * GSTAGE + 3*GARR ) * 2;

        #pragma unroll
        for (int kk = 0; kk < 2; kk++) {
            const int kc0 = kk * 16;
            uint32_t aH[4][4], tA[4][4], bH[16], tB[16];

            #pragma unroll
            for (int mt = 0; mt < 4; mt++)
                ldsm4(aH[mt], Ahb +
                    (uint32_t)((warpM + mt*16 + a_r) * GPAD + kc0 + a_c) * 2);
            #pragma unroll
            for (int p = 0; p < 4; p++)
                ldsm4(&bH[p*4], Bhb +
                    (uint32_t)((warpN + p*16 + b_r) * GPAD + kc0 + b_c) * 2);

            #pragma unroll
            for (int mt = 0; mt < 4; mt++)
                #pragma unroll
                for (int nt = 0; nt < 8; nt++)
                    mma16816(c[mt][nt], aH[mt], &bH[nt * 2]);

            #pragma unroll
            for (int p = 0; p < 4; p++)
                ldsm4(&tB[p*4], Blb +
                    (uint32_t)((warpN + p*16 + b_r) * GPAD + kc0 + b_c) * 2);
            #pragma unroll
            for (int mt = 0; mt < 4; mt++)
                #pragma unroll
                for (int nt = 0; nt < 8; nt++)
                    mma16816(c[mt][nt], aH[mt], &tB[nt * 2]);

            #pragma unroll
            for (int mt = 0; mt < 4; mt++)
                ldsm4(tA[mt], Alb +
                    (uint32_t)((warpM + mt*16 + a_r) * GPAD + kc0 + a_c) * 2);
            #pragma unroll
            for (int mt = 0; mt < 4; mt++)
                #pragma unroll
                for (int nt = 0; nt < 8; nt++)
                    mma16816(c[mt][nt], tA[mt], &bH[nt * 2]);
        }
        s ^= 1;
    }

    #pragma unroll
    for (int mt = 0; mt < 4; mt++) {
        const int r0 = m0 + warpM + mt * 16 + gq;
        #pragma unroll
        for (int nt = 0; nt < 8; nt++) {
            const int col = n0 + warpN + nt * 8 + qt * 2;
            const float2 bb = *(const float2*)&bias[col];
            float* cc = c[mt][nt];
            const float v0 = cc[0] + bb.x, v1 = cc[1] + bb.y;
            const float v2 = cc[2] + bb.x, v3 = cc[3] + bb.y;
            if (Ch) {
                uint32_t h0 = pack_bf16(v0, v1);
                uint32_t h1 = pack_bf16(v2, v3);
                __nv_bfloat162 H0 = *(__nv_bfloat162*)&h0;
                __nv_bfloat162 H1 = *(__nv_bfloat162*)&h1;
                uint32_t l0 = pack_bf16(v0 - __bfloat162float(H0.x),
                                        v1 - __bfloat162float(H0.y));
                uint32_t l1 = pack_bf16(v2 - __bfloat162float(H1.x),
                                        v3 - __bfloat162float(H1.y));
                *(uint32_t*)&Ch[(size_t)r0 * N + col]       = h0;
                *(uint32_t*)&Cl[(size_t)r0 * N + col]       = l0;
                *(uint32_t*)&Ch[(size_t)(r0 + 8) * N + col] = h1;
                *(uint32_t*)&Cl[(size_t)(r0 + 8) * N + col] = l1;
            } else {
                *(float2*)&Cf[(size_t)r0 * N + col]       = make_float2(v0, v1);
                *(float2*)&Cf[(size_t)(r0 + 8) * N + col] = make_float2(v2, v3);
            }
        }
    }
}

// ===========================================================================
// Tensor-core flash attention; 8 warps x 32 query rows, q-tile 256, 1 CTA/SM.
// Single-barrier pipelined K/V loop (same reorder as gemm_tc).
// ===========================================================================
#define APAD 72
#define AARR (64 * APAD)            // 4608 el
#define ASTAGE (4 * AARR)           // 36864 B
#define ATTN_SMEM (2 * ASTAGE * 2)  // 73728 B dynamic (Q 256x72 hi+lo overlays)

__global__ __launch_bounds__(256, 1) void attn_tc(
    const __nv_bfloat16* __restrict__ qh, const __nv_bfloat16* __restrict__ ql,
    const float* __restrict__ dd,
    __nv_bfloat16* __restrict__ outh, __nv_bfloat16* __restrict__ outl)
{
    extern __shared__ __nv_bfloat16 sm[];
    __shared__ float dtab[2048];
    const uint32_t smb = smem_u32(sm);

    const int tid = threadIdx.x;
    const int wid = tid >> 5;
    const int lid = tid & 31;
    const int gq  = lid >> 2;
    const int qt  = lid & 3;
    const int q0 = blockIdx.x * 256;
    const int h  = blockIdx.y;
    const int b  = blockIdx.z;

    const float na = fabsf(dd[0]);
    #pragma unroll
    for (int t = tid; t < 2048; t += 256)
        dtab[t] = __expf(-na * (float)t);

    const size_t rowbase = (size_t)b * S_;
    const int colQ = h * D_;
    const int colK = colQ + E_;
    const int colV = colQ + 2 * E_;

    const int k_r = (lid & 7) + ((lid & 16) ? 8 : 0);
    const int k_c = (lid & 8) ? 8 : 0;
    const int t_loc = (lid & 7) + (lid & 8);
    const int d_grp = (lid & 16) >> 1;

    // ---- stage Q (hi 256x64 + lo) overlaying the K/V region ----
    #pragma unroll
    for (int it = 0; it < 16; it++) {
        const int idx = tid + it * 256;
        const int arr = idx >> 11;
        const int i   = idx & 2047;
        const int row = i >> 3, seg = (i & 7) * 8;
        const __nv_bfloat16* src = (arr ? ql : qh)
            + (rowbase + q0 + row) * E3_ + colQ + seg;
        cp_async16(smb + (uint32_t)(arr * 256 * APAD + row * APAD + seg) * 2, src);
    }
    CP_COMMIT(); CP_WAIT_0();
    __syncthreads();

    uint32_t aQh[2][4][4], aQl[2][4][4];
    {
        const int a_r = (lid & 7) + ((lid & 8) ? 8 : 0);
        const int a_c = (lid & 16) ? 8 : 0;
        const uint32_t Qhb = smb;
        const uint32_t Qlb = smb + (uint32_t)(256 * APAD) * 2;
        #pragma unroll
        for (int mt = 0; mt < 2; mt++) {
            const int rr = wid * 32 + mt * 16 + a_r;
            #pragma unroll
            for (int kc = 0; kc < 4; kc++) {
                ldsm4(aQh[mt][kc], Qhb + (uint32_t)(rr * APAD + kc*16 + a_c) * 2);
                ldsm4(aQl[mt][kc], Qlb + (uint32_t)(rr * APAD + kc*16 + a_c) * 2);
            }
        }
    }
    __syncthreads();   // Q region free for K/V staging

    auto stageKV = [&](int s, int k0) {
        const uint32_t base = smb + (uint32_t)(s * ASTAGE) * 2;
        #pragma unroll
        for (int it = 0; it < 8; it++) {
            const int idx = tid + it * 256;
            const int arr = idx >> 9;
            const int i   = idx & 511;
            const int row = i >> 3, seg = (i & 7) * 8;
            const int col = (arr < 2 ? colK : colV) + seg;
            const __nv_bfloat16* src = ((arr & 1) ? ql : qh)
                + (rowbase + k0 + row) * E3_ + col;
            cp_async16(base + (uint32_t)(arr * AARR + row * APAD + seg) * 2, src);
        }
    };

    float m_i[4] = {-INFINITY, -INFINITY, -INFINITY, -INFINITY};
    float l_i[4] = {0.f, 0.f, 0.f, 0.f};
    float O[2][8][4];
    #pragma unroll
    for (int mt = 0; mt < 2; mt++)
        #pragma unroll
        for (int nt = 0; nt < 8; nt++)
            O[mt][nt][0] = O[mt][nt][1] = O[mt][nt][2] = O[mt][nt][3] = 0.f;

    const int qrow0 = q0 + wid * 32 + gq;

    stageKV(0, 0);
    CP_COMMIT();

    int s = 0;
    for (int k0 = 0; k0 < S_; k0 += 64) {
        CP_WAIT_0();          // this tile's K/V landed (per-thread)
        __syncthreads();      // all threads landed; prev compute done

        if (k0 + 64 < S_) { stageKV(s ^ 1, k0 + 64); CP_COMMIT(); }

        const uint32_t Khb = smb + (uint32_t)(s * ASTAGE          ) * 2;
        const uint32_t Klb = smb + (uint32_t)(s * ASTAGE + 1*AARR ) * 2;
        const uint32_t vhb = smb + (uint32_t)(s * ASTAGE + 2*AARR ) * 2;
        const uint32_t vlb = smb + (uint32_t)(s * ASTAGE + 3*AARR ) * 2;

        // ---- S = Q K^T for both m-tiles; K fragments loaded once ----
        float S[2][8][4];
        #pragma unroll
        for (int mt = 0; mt < 2; mt++)
            #pragma unroll
            for (int i = 0; i < 8; i++)
                S[mt][i][0] = S[mt][i][1] = S[mt][i][2] = S[mt][i][3] = 0.f;

        #pragma unroll
        for (int kc = 0; kc < 4; kc++) {
            #pragma unroll
            for (int p = 0; p < 4; p++) {
                const uint32_t off =
                    (uint32_t)((p * 16 + k_r) * APAD + kc * 16 + k_c) * 2;
                uint32_t kh4[4], kl4[4];
                ldsm4(kh4, Khb + off);
                ldsm4(kl4, Klb + off);
                #pragma unroll
                for (int mt = 0; mt < 2; mt++) {
                    mma16816(S[mt][2*p],     aQh[mt][kc], &kh4[0]);
                    mma16816(S[mt][2*p],     aQh[mt][kc], &kl4[0]);
                    mma16816(S[mt][2*p],     aQl[mt][kc], &kh4[0]);
                    mma16816(S[mt][2*p + 1], aQh[mt][kc], &kh4[2]);
                    mma16816(S[mt][2*p + 1], aQh[mt][kc], &kl4[2]);
                    mma16816(S[mt][2*p + 1], aQl[mt][kc], &kh4[2]);
                }
            }
        }

        // ---- scale * decay + online softmax, per m-tile ----
        #pragma unroll
        for (int mt = 0; mt < 2; mt++) {
            const int qr = qrow0 + mt * 16;
            float rm0 = -INFINITY, rm1 = -INFINITY;
            #pragma unroll
            for (int nt = 0; nt < 8; nt++) {
                const int kcol = k0 + nt * 8 + qt * 2;
                float* Sv = S[mt][nt];
                Sv[0] *= 0.125f * dtab[abs(qr - kcol)];
                Sv[1] *= 0.125f * dtab[abs(qr - kcol - 1)];
                Sv[2] *= 0.125f * dtab[abs(qr + 8 - kcol)];
                Sv[3] *= 0.125f * dtab[abs(qr + 8 - kcol - 1)];
                rm0 = fmaxf(rm0, fmaxf(Sv[0], Sv[1]));
                rm1 = fmaxf(rm1, fmaxf(Sv[2], Sv[3]));
            }
            rm0 = fmaxf(rm0, __shfl_xor_sync(0xffffffffu, rm0, 1));
            rm0 = fmaxf(rm0, __shfl_xor_sync(0xffffffffu, rm0, 2));
            rm1 = fmaxf(rm1, __shfl_xor_sync(0xffffffffu, rm1, 1));
            rm1 = fmaxf(rm1, __shfl_xor_sync(0xffffffffu, rm1, 2));

            const float mn0 = fmaxf(m_i[2*mt],     rm0);
            const float mn1 = fmaxf(m_i[2*mt + 1], rm1);
            const float sc0 = __expf(m_i[2*mt]     - mn0);
            const float sc1 = __expf(m_i[2*mt + 1] - mn1);

            float rs0 = 0.f, rs1 = 0.f;
            #pragma unroll
            for (int nt = 0; nt < 8; nt++) {
                float* Sv = S[mt][nt];
                Sv[0] = __expf(Sv[0] - mn0);
                Sv[1] = __expf(Sv[1] - mn0);
                Sv[2] = __expf(Sv[2] - mn1);
                Sv[3] = __expf(Sv[3] - mn1);
                rs0 += Sv[0] + Sv[1];
                rs1 += Sv[2] + Sv[3];
            }
            rs0 += __shfl_xor_sync(0xffffffffu, rs0, 1);
            rs0 += __shfl_xor_sync(0xffffffffu, rs0, 2);
            rs1 += __shfl_xor_sync(0xffffffffu, rs1, 1);
            rs1 += __shfl_xor_sync(0xffffffffu, rs1, 2);

            l_i[2*mt]     = l_i[2*mt]     * sc0 + rs0;
            l_i[2*mt + 1] = l_i[2*mt + 1] * sc1 + rs1;
            m_i[2*mt]     = mn0;
            m_i[2*mt + 1] = mn1;

            #pragma unroll
            for (int nt = 0; nt < 8; nt++) {
                O[mt][nt][0] *= sc0; O[mt][nt][1] *= sc0;
                O[mt][nt][2] *= sc1; O[mt][nt][3] *= sc1;
            }
        }

        // ---- PV: per j-chunk, pack P (both m-tiles) then share V frags ----
        #pragma unroll
        for (int j = 0; j < 4; j++) {
            uint32_t aPh2[2][4], aPl2[2][4];
            #pragma unroll
            for (int mt = 0; mt < 2; mt++) {
                const float* s0 = S[mt][2 * j];
                const float* s1 = S[mt][2 * j + 1];
                aPh2[mt][0] = pack_bf16(s0[0], s0[1]);
                aPh2[mt][1] = pack_bf16(s0[2], s0[3]);
                aPh2[mt][2] = pack_bf16(s1[0], s1[1]);
                aPh2[mt][3] = pack_bf16(s1[2], s1[3]);
                __nv_bfloat162 h0 = *(__nv_bfloat162*)&aPh2[mt][0];
                __nv_bfloat162 h1 = *(__nv_bfloat162*)&aPh2[mt][1];
                __nv_bfloat162 h2 = *(__nv_bfloat162*)&aPh2[mt][2];
                __nv_bfloat162 h3 = *(__nv_bfloat162*)&aPh2[mt][3];
                aPl2[mt][0] = pack_bf16(s0[0] - __bfloat162float(h0.x),
                                        s0[1] - __bfloat162float(h0.y));
                aPl2[mt][1] = pack_bf16(s0[2] - __bfloat162float(h1.x),
                                        s0[3] - __bfloat162float(h1.y));
                aPl2[mt][2] = pack_bf16(s1[0] - __bfloat162float(h2.x),
                                        s1[1] - __bfloat162float(h2.y));
                aPl2[mt][3] = pack_bf16(s1[2] - __bfloat162float(h3.x),
                                        s1[3] - __bfloat162float(h3.y));
            }
            #pragma unroll
            for (int db = 0; db < 4; db++) {
                const uint32_t off =
                    (uint32_t)((j * 16 + t_loc) * APAD + db * 16 + d_grp) * 2;
                uint32_t vh[4], vl[4];
                ldsm4t(vh, vhb + off);
                ldsm4t(vl, vlb + off);
                #pragma unroll
                for (int mt = 0; mt < 2; mt++) {
                    mma16816(O[mt][2 * db],     aPh2[mt], &vh[0]);
                    mma16816(O[mt][2 * db],     aPh2[mt], &vl[0]);
                    mma16816(O[mt][2 * db],     aPl2[mt], &vh[0]);
                    mma16816(O[mt][2 * db + 1], aPh2[mt], &vh[2]);
                    mma16816(O[mt][2 * db + 1], aPh2[mt], &vl[2]);
                    mma16816(O[mt][2 * db + 1], aPl2[mt], &vh[2]);
                }
            }
        }
        s ^= 1;
    }

    // ---- epilogue: split-bf16 output ----
    #pragma unroll
    for (int mt = 0; mt < 2; mt++) {
        const float inv0 = 1.0f / l_i[2*mt];
        const float inv1 = 1.0f / l_i[2*mt + 1];
        const size_t r0 = rowbase + qrow0 + mt * 16;
        #pragma unroll
        for (int nt = 0; nt < 8; nt++) {
            const int col = h * D_ + nt * 8 + qt * 2;
            const float v0 = O[mt][nt][0] * inv0, v1 = O[mt][nt][1] * inv0;
            const float v2 = O[mt][nt][2] * inv1, v3 = O[mt][nt][3] * inv1;
            uint32_t h0 = pack_bf16(v0, v1);
            uint32_t h1 = pack_bf16(v2, v3);
            __nv_bfloat162 H0 = *(__nv_bfloat162*)&h0;
            __nv_bfloat162 H1 = *(__nv_bfloat162*)&h1;
            uint32_t l0 = pack_bf16(v0 - __bfloat162float(H0.x),
                                    v1 - __bfloat162float(H0.y));
            uint32_t l1 = pack_bf16(v2 - __bfloat162float(H1.x),
                                    v3 - __bfloat162float(H1.y));
            *(uint32_t*)&outh[r0 * E_ + col]       = h0;
            *(uint32_t*)&outl[r0 * E_ + col]       = l0;
            *(uint32_t*)&outh[(r0 + 8) * E_ + col] = h1;
            *(uint32_t*)&outl[(r0 + 8) * E_ + col] = l1;
        }
    }
}

// ===========================================================================
extern "C" void kernel_launch(void* const* d_in, const int* in_sizes, int n_in,
                              void* d_out, int out_size)
{
    const float* x      = (const float*)d_in[0];
    const float* Wqkv_w = (const float*)d_in[1];
    const float* Wqkv_b = (const float*)d_in[2];
    const float* out_w  = (const float*)d_in[3];
    const float* out_b  = (const float*)d_in[4];
    const float* dd     = (const float*)d_in[5];
    float* out = (float*)d_out;

    __nv_bfloat16 *xh, *xl, *wqh, *wql, *owh, *owl, *qkvh, *qkvl, *ath, *atl;
    cudaGetSymbolAddress((void**)&xh,  g_xh);  cudaGetSymbolAddress((void**)&xl,  g_xl);
    cudaGetSymbolAddress((void**)&wqh, g_wqh); cudaGetSymbolAddress((void**)&wql, g_wql);
    cudaGetSymbolAddress((void**)&owh, g_owh); cudaGetSymbolAddress((void**)&owl, g_owl);
    cudaGetSymbolAddress((void**)&qkvh, g_qkvh); cudaGetSymbolAddress((void**)&qkvl, g_qkvl);
    cudaGetSymbolAddress((void**)&ath, g_ath); cudaGetSymbolAddress((void**)&atl, g_atl);

    cudaFuncSetAttribute(gemm_tc, cudaFuncAttributeMaxDynamicSharedMemorySize,
                         GEMM_SMEM);
    cudaFuncSetAttribute(attn_tc, cudaFuncAttributeMaxDynamicSharedMemorySize,
                         ATTN_SMEM);

    // 0. split inputs/weights to bf16 hi/lo
    split_bf16<<<(M_ * E_ / 4 + 255) / 256, 256>>>(x, xh, xl, M_ * E_ / 4);
    split_bf16<<<(E3_ * E_ / 4 + 255) / 256, 256>>>(Wqkv_w, wqh, wql, E3_ * E_ / 4);
    split_bf16<<<(E_ * E_ / 4 + 255) / 256, 256>>>(out_w, owh, owl, E_ * E_ / 4);

    // 1. QKV projection -> split bf16 qkv
    gemm_tc<<<dim3(E3_ / 128, M_ / 128), 128, GEMM_SMEM>>>(
        xh, xl, wqh, wql, Wqkv_b, nullptr, qkvh, qkvl, M_, E3_, E_);

    // 2. attention -> split bf16 attn out (q-tile 256)
    attn_tc<<<dim3(S_ / 256, H_, B_), 256, ATTN_SMEM>>>(qkvh, qkvl, dd, ath, atl);

    // 3. output projection -> fp32 out
    gemm_tc<<<dim3(E_ / 128, M_ / 128), 128, GEMM_SMEM>>>(
        ath, atl, owh, owl, out_b, out, nullptr, nullptr, M_, E_, E_);
}

// round 17
// speedup vs baseline: 1.5906x; 1.5906x over previous
#include <cuda_runtime.h>
#include <cuda_bf16.h>
#include <math.h>
#include <stdint.h>

#define B_  2
#define S_  2048
#define E_  1024
#define H_  16
#define D_  64
#define E3_ 3072
#define M_  (B_ * S_)   // 4096
#define NT_ (S_ / 64)   // 32 key tiles

// ---------------- device-global scratch (allocation-free rule) -------------
__device__ __nv_bfloat16 g_xh [(size_t)M_  * E_ ], g_xl [(size_t)M_  * E_ ];
__device__ __nv_bfloat16 g_wqh[(size_t)E3_ * E_ ], g_wql[(size_t)E3_ * E_ ];
__device__ __nv_bfloat16 g_owh[(size_t)E_  * E_ ], g_owl[(size_t)E_  * E_ ];
__device__ __nv_bfloat16 g_qkvh[(size_t)M_ * E3_], g_qkvl[(size_t)M_ * E3_];
__device__ __nv_bfloat16 g_ath[(size_t)M_  * E_ ], g_atl[(size_t)M_  * E_ ];
__device__ float g_vts[(size_t)B_ * H_ * NT_ * D_];   // per-tile V column sums

// ---------------- PTX helpers (baseline ISA only) --------------------------
__device__ __forceinline__ void mma16816(float* c, const uint32_t* a,
                                         const uint32_t* b) {
    asm volatile(
        "mma.sync.aligned.m16n8k16.row.col.f32.bf16.bf16.f32 "
        "{%0,%1,%2,%3}, {%4,%5,%6,%7}, {%8,%9}, {%0,%1,%2,%3};"
        : "+f"(c[0]), "+f"(c[1]), "+f"(c[2]), "+f"(c[3])
        : "r"(a[0]), "r"(a[1]), "r"(a[2]), "r"(a[3]), "r"(b[0]), "r"(b[1]));
}

__device__ __forceinline__ uint32_t pack_bf16(float a, float b) {
    __nv_bfloat162 h = __floats2bfloat162_rn(a, b);
    return *(uint32_t*)&h;
}

__device__ __forceinline__ uint32_t smem_u32(const void* p) {
    uint32_t a;
    asm("{ .reg .u64 t; cvta.to.shared.u64 t, %1; cvt.u32.u64 %0, t; }"
        : "=r"(a) : "l"(p));
    return a;
}

__device__ __forceinline__ void cp_async16(uint32_t dst, const void* src) {
    asm volatile("cp.async.ca.shared.global [%0], [%1], 16;"
                 :: "r"(dst), "l"(src));
}
#define CP_COMMIT() asm volatile("cp.async.commit_group;" ::: "memory")
#define CP_WAIT_0() asm volatile("cp.async.wait_group 0;" ::: "memory")

__device__ __forceinline__ void ldsm4(uint32_t* r, uint32_t addr) {
    asm volatile(
        "ldmatrix.sync.aligned.m8n8.x4.shared.b16 {%0,%1,%2,%3}, [%4];"
        : "=r"(r[0]), "=r"(r[1]), "=r"(r[2]), "=r"(r[3]) : "r"(addr));
}
__device__ __forceinline__ void ldsm4t(uint32_t* r, uint32_t addr) {
    asm volatile(
        "ldmatrix.sync.aligned.m8n8.x4.trans.shared.b16 {%0,%1,%2,%3}, [%4];"
        : "=r"(r[0]), "=r"(r[1]), "=r"(r[2]), "=r"(r[3]) : "r"(addr));
}

// ---------------- split fp32 -> bf16 hi/lo ---------------------------------
__global__ __launch_bounds__(256) void split_bf16(
    const float* __restrict__ src, __nv_bfloat16* __restrict__ hi,
    __nv_bfloat16* __restrict__ lo, int n4)
{
    const int i = blockIdx.x * 256 + threadIdx.x;
    if (i >= n4) return;
    float4 v = ((const float4*)src)[i];
    uint32_t h0 = pack_bf16(v.x, v.y);
    uint32_t h1 = pack_bf16(v.z, v.w);
    __nv_bfloat162 H0 = *(__nv_bfloat162*)&h0;
    __nv_bfloat162 H1 = *(__nv_bfloat162*)&h1;
    uint32_t l0 = pack_bf16(v.x - __bfloat162float(H0.x),
                            v.y - __bfloat162float(H0.y));
    uint32_t l1 = pack_bf16(v.z - __bfloat162float(H1.x),
                            v.w - __bfloat162float(H1.y));
    ((uint2*)hi)[i] = make_uint2(h0, h1);
    ((uint2*)lo)[i] = make_uint2(l0, l1);
}

// ---------------- per-tile V column sums ------------------------------------
// grid (NT_, H_, B_), block 64.  g_vts[((b*H+h)*NT + t)*64 + d] = sum_r V[t*64+r][d]
__global__ __launch_bounds__(64) void vtile_sum(
    const __nv_bfloat16* __restrict__ qh, const __nv_bfloat16* __restrict__ ql)
{
    const int d = threadIdx.x;
    const int t = blockIdx.x, h = blockIdx.y, b = blockIdx.z;
    const size_t rowbase = (size_t)b * S_ + t * 64;
    const int col = h * D_ + 2 * E_ + d;
    float s = 0.f;
    #pragma unroll 8
    for (int r = 0; r < 64; r++) {
        const size_t off = (rowbase + r) * E3_ + col;
        s += __bfloat162float(qh[off]) + __bfloat162float(ql[off]);
    }
    g_vts[(((size_t)b * H_ + h) * NT_ + t) * 64 + d] = s;
}

// ===========================================================================
// Split-bf16 HMMA GEMM; 4 warps (2x2), 64x64 warp tiles, 2 CTA/SM.
// (unchanged)
// ===========================================================================
#define GPAD 40
#define GARR (128 * GPAD)
#define GSTAGE (4 * GARR)
#define GEMM_SMEM (2 * GSTAGE * 2)

__global__ __launch_bounds__(128, 2) void gemm_tc(
    const __nv_bfloat16* __restrict__ Ahg, const __nv_bfloat16* __restrict__ Alg,
    const __nv_bfloat16* __restrict__ Bhg, const __nv_bfloat16* __restrict__ Blg,
    const float* __restrict__ bias,
    float* __restrict__ Cf, __nv_bfloat16* __restrict__ Ch,
    __nv_bfloat16* __restrict__ Cl,
    int M, int N, int K)
{
    extern __shared__ __nv_bfloat16 sm[];
    const uint32_t smb = smem_u32(sm);

    const int tid = threadIdx.x;
    const int wid = tid >> 5;
    const int lid = tid & 31;
    const int gq  = lid >> 2;
    const int qt  = lid & 3;
    const int m0 = blockIdx.y * 128;
    const int n0 = blockIdx.x * 128;
    const int warpM = (wid >> 1) * 64;
    const int warpN = (wid & 1) * 64;

    const int a_r = (lid & 7) + ((lid & 8)  ? 8 : 0);
    const int a_c = (lid & 16) ? 8 : 0;
    const int b_r = (lid & 7) + ((lid & 16) ? 8 : 0);
    const int b_c = (lid & 8) ? 8 : 0;

    float c[4][8][4];
    #pragma unroll
    for (int mt = 0; mt < 4; mt++)
        #pragma unroll
        for (int nt = 0; nt < 8; nt++)
            c[mt][nt][0] = c[mt][nt][1] = c[mt][nt][2] = c[mt][nt][3] = 0.f;

    int srow[4], sseg[4];
    #pragma unroll
    for (int i = 0; i < 4; i++) {
        const int idx = tid + i * 128;
        srow[i] = idx >> 2;
        sseg[i] = (idx & 3) * 8;
    }

    auto stage = [&](int s, int kb) {
        const uint32_t base = smb + (uint32_t)(s * GSTAGE) * 2;
        #pragma unroll
        for (int i = 0; i < 4; i++) {
            const int r = srow[i], g = sseg[i];
            cp_async16(base + (uint32_t)(0*GARR + r*GPAD + g)*2,
                       &Ahg[(size_t)(m0 + r) * K + kb + g]);
            cp_async16(base + (uint32_t)(1*GARR + r*GPAD + g)*2,
                       &Alg[(size_t)(m0 + r) * K + kb + g]);
            cp_async16(base + (uint32_t)(2*GARR + r*GPAD + g)*2,
                       &Bhg[(size_t)(n0 + r) * K + kb + g]);
            cp_async16(base + (uint32_t)(3*GARR + r*GPAD + g)*2,
                       &Blg[(size_t)(n0 + r) * K + kb + g]);
        }
    };

    stage(0, 0);
    CP_COMMIT();

    int s = 0;
    for (int kb = 0; kb < K; kb += 32) {
        CP_WAIT_0();
        __syncthreads();

        if (kb + 32 < K) { stage(s ^ 1, kb + 32); CP_COMMIT(); }

        const uint32_t Ahb = smb + (uint32_t)(s * GSTAGE          ) * 2;
        const uint32_t Alb = smb + (uint32_t)(s * GSTAGE + 1*GARR ) * 2;
        const uint32_t Bhb = smb + (uint32_t)(s * GSTAGE + 2*GARR ) * 2;
        const uint32_t Blb = smb + (uint32_t)(s * GSTAGE + 3*GARR ) * 2;

        #pragma unroll
        for (int kk = 0; kk < 2; kk++) {
            const int kc0 = kk * 16;
            uint32_t aH[4][4], tA[4][4], bH[16], tB[16];

            #pragma unroll
            for (int mt = 0; mt < 4; mt++)
                ldsm4(aH[mt], Ahb +
                    (uint32_t)((warpM + mt*16 + a_r) * GPAD + kc0 + a_c) * 2);
            #pragma unroll
            for (int p = 0; p < 4; p++)
                ldsm4(&bH[p*4], Bhb +
                    (uint32_t)((warpN + p*16 + b_r) * GPAD + kc0 + b_c) * 2);

            #pragma unroll
            for (int mt = 0; mt < 4; mt++)
                #pragma unroll
                for (int nt = 0; nt < 8; nt++)
                    mma16816(c[mt][nt], aH[mt], &bH[nt * 2]);

            #pragma unroll
            for (int p = 0; p < 4; p++)
                ldsm4(&tB[p*4], Blb +
                    (uint32_t)((warpN + p*16 + b_r) * GPAD + kc0 + b_c) * 2);
            #pragma unroll
            for (int mt = 0; mt < 4; mt++)
                #pragma unroll
                for (int nt = 0; nt < 8; nt++)
                    mma16816(c[mt][nt], aH[mt], &tB[nt * 2]);

            #pragma unroll
            for (int mt = 0; mt < 4; mt++)
                ldsm4(tA[mt], Alb +
                    (uint32_t)((warpM + mt*16 + a_r) * GPAD + kc0 + a_c) * 2);
            #pragma unroll
            for (int mt = 0; mt < 4; mt++)
                #pragma unroll
                for (int nt = 0; nt < 8; nt++)
                    mma16816(c[mt][nt], tA[mt], &bH[nt * 2]);
        }
        s ^= 1;
    }

    #pragma unroll
    for (int mt = 0; mt < 4; mt++) {
        const int r0 = m0 + warpM + mt * 16 + gq;
        #pragma unroll
        for (int nt = 0; nt < 8; nt++) {
            const int col = n0 + warpN + nt * 8 + qt * 2;
            const float2 bb = *(const float2*)&bias[col];
            float* cc = c[mt][nt];
            const float v0 = cc[0] + bb.x, v1 = cc[1] + bb.y;
            const float v2 = cc[2] + bb.x, v3 = cc[3] + bb.y;
            if (Ch) {
                uint32_t h0 = pack_bf16(v0, v1);
                uint32_t h1 = pack_bf16(v2, v3);
                __nv_bfloat162 H0 = *(__nv_bfloat162*)&h0;
                __nv_bfloat162 H1 = *(__nv_bfloat162*)&h1;
                uint32_t l0 = pack_bf16(v0 - __bfloat162float(H0.x),
                                        v1 - __bfloat162float(H0.y));
                uint32_t l1 = pack_bf16(v2 - __bfloat162float(H1.x),
                                        v3 - __bfloat162float(H1.y));
                *(uint32_t*)&Ch[(size_t)r0 * N + col]       = h0;
                *(uint32_t*)&Cl[(size_t)r0 * N + col]       = l0;
                *(uint32_t*)&Ch[(size_t)(r0 + 8) * N + col] = h1;
                *(uint32_t*)&Cl[(size_t)(r0 + 8) * N + col] = l1;
            } else {
                *(float2*)&Cf[(size_t)r0 * N + col]       = make_float2(v0, v1);
                *(float2*)&Cf[(size_t)(r0 + 8) * N + col] = make_float2(v2, v3);
            }
        }
    }
}

// ===========================================================================
// Banded tensor-core flash attention with closed-form far-field.
// Far keys (decay underflow): logit = 0 exactly -> weight e^{-m}, handled via
// precomputed per-tile V sums.  Band = [klo, khi) covers decay >= ~1e-6.
// ===========================================================================
#define APAD 72
#define AARR (64 * APAD)            // 4608 el
#define ASTAGE (4 * AARR)           // 36864 B
#define ATTN_SMEM (2 * ASTAGE * 2)  // 73728 B dynamic (Q 256x72 hi+lo overlays)

__global__ __launch_bounds__(256, 1) void attn_tc(
    const __nv_bfloat16* __restrict__ qh, const __nv_bfloat16* __restrict__ ql,
    const float* __restrict__ dd,
    __nv_bfloat16* __restrict__ outh, __nv_bfloat16* __restrict__ outl)
{
    extern __shared__ __nv_bfloat16 sm[];
    __shared__ float dtab[2048];
    __shared__ float farV[64];
    const uint32_t smb = smem_u32(sm);

    const int tid = threadIdx.x;
    const int wid = tid >> 5;
    const int lid = tid & 31;
    const int gq  = lid >> 2;
    const int qt  = lid & 3;
    const int q0 = blockIdx.x * 256;
    const int h  = blockIdx.y;
    const int b  = blockIdx.z;

    const float na = fabsf(dd[0]);
    #pragma unroll
    for (int t = tid; t < 2048; t += 256)
        dtab[t] = __expf(-na * (float)t);

    // band: decay(dist) >= ~exp(-14) outside is zero to ~1e-6 absolute logit
    const int dth = (na > 1e-7f) ? min(S_, (int)ceilf(14.0f / na)) : S_;
    const int klo = max(0, q0 - dth) & ~63;
    const int khi = min(S_, (q0 + 256 + dth + 63) & ~63);
    const int nfar = S_ - (khi - klo);

    const size_t rowbase = (size_t)b * S_;
    const int colQ = h * D_;
    const int colK = colQ + E_;
    const int colV = colQ + 2 * E_;

    // far-field V column sums (tiles outside band)
    if (tid < 64) {
        float fv = 0.f;
        const float* vts = &g_vts[(((size_t)b * H_ + h) * NT_) * 64 + tid];
        for (int t = 0; t < NT_; t++) {
            const int k = t * 64;
            if (k < klo || k >= khi) fv += vts[(size_t)t * 64];
            vts += 0;   // (indexing below)
        }
        // note: vts index per tile:
        farV[tid] = 0.f;
        fv = 0.f;
        for (int t = 0; t < NT_; t++) {
            const int k = t * 64;
            if (k < klo || k >= khi)
                fv += g_vts[(((size_t)b * H_ + h) * NT_ + t) * 64 + tid];
        }
        farV[tid] = fv;
    }

    const int k_r = (lid & 7) + ((lid & 16) ? 8 : 0);
    const int k_c = (lid & 8) ? 8 : 0;
    const int t_loc = (lid & 7) + (lid & 8);
    const int d_grp = (lid & 16) >> 1;

    // ---- stage Q (hi 256x64 + lo) overlaying the K/V region ----
    #pragma unroll
    for (int it = 0; it < 16; it++) {
        const int idx = tid + it * 256;
        const int arr = idx >> 11;
        const int i   = idx & 2047;
        const int row = i >> 3, seg = (i & 7) * 8;
        const __nv_bfloat16* src = (arr ? ql : qh)
            + (rowbase + q0 + row) * E3_ + colQ + seg;
        cp_async16(smb + (uint32_t)(arr * 256 * APAD + row * APAD + seg) * 2, src);
    }
    CP_COMMIT(); CP_WAIT_0();
    __syncthreads();

    uint32_t aQh[2][4][4], aQl[2][4][4];
    {
        const int a_r = (lid & 7) + ((lid & 8) ? 8 : 0);
        const int a_c = (lid & 16) ? 8 : 0;
        const uint32_t Qhb = smb;
        const uint32_t Qlb = smb + (uint32_t)(256 * APAD) * 2;
        #pragma unroll
        for (int mt = 0; mt < 2; mt++) {
            const int rr = wid * 32 + mt * 16 + a_r;
            #pragma unroll
            for (int kc = 0; kc < 4; kc++) {
                ldsm4(aQh[mt][kc], Qhb + (uint32_t)(rr * APAD + kc*16 + a_c) * 2);
                ldsm4(aQl[mt][kc], Qlb + (uint32_t)(rr * APAD + kc*16 + a_c) * 2);
            }
        }
    }
    __syncthreads();   // Q region free for K/V staging

    auto stageKV = [&](int s, int k0) {
        const uint32_t base = smb + (uint32_t)(s * ASTAGE) * 2;
        #pragma unroll
        for (int it = 0; it < 8; it++) {
            const int idx = tid + it * 256;
            const int arr = idx >> 9;
            const int i   = idx & 511;
            const int row = i >> 3, seg = (i & 7) * 8;
            const int col = (arr < 2 ? colK : colV) + seg;
            const __nv_bfloat16* src = ((arr & 1) ? ql : qh)
                + (rowbase + k0 + row) * E3_ + col;
            cp_async16(base + (uint32_t)(arr * AARR + row * APAD + seg) * 2, src);
        }
    };

    // m init 0: far keys have logit exactly 0, so the running max includes it.
    float m_i[4] = {0.f, 0.f, 0.f, 0.f};
    float l_i[4] = {0.f, 0.f, 0.f, 0.f};
    float O[2][8][4];
    #pragma unroll
    for (int mt = 0; mt < 2; mt++)
        #pragma unroll
        for (int nt = 0; nt < 8; nt++)
            O[mt][nt][0] = O[mt][nt][1] = O[mt][nt][2] = O[mt][nt][3] = 0.f;

    const int qrow0 = q0 + wid * 32 + gq;

    stageKV(0, klo);
    CP_COMMIT();

    int s = 0;
    for (int k0 = klo; k0 < khi; k0 += 64) {
        CP_WAIT_0();
        __syncthreads();

        if (k0 + 64 < khi) { stageKV(s ^ 1, k0 + 64); CP_COMMIT(); }

        const uint32_t Khb = smb + (uint32_t)(s * ASTAGE          ) * 2;
        const uint32_t Klb = smb + (uint32_t)(s * ASTAGE + 1*AARR ) * 2;
        const uint32_t vhb = smb + (uint32_t)(s * ASTAGE + 2*AARR ) * 2;
        const uint32_t vlb = smb + (uint32_t)(s * ASTAGE + 3*AARR ) * 2;

        float S[2][8][4];
        #pragma unroll
        for (int mt = 0; mt < 2; mt++)
            #pragma unroll
            for (int i = 0; i < 8; i++)
                S[mt][i][0] = S[mt][i][1] = S[mt][i][2] = S[mt][i][3] = 0.f;

        #pragma unroll
        for (int kc = 0; kc < 4; kc++) {
            #pragma unroll
            for (int p = 0; p < 4; p++) {
                const uint32_t off =
                    (uint32_t)((p * 16 + k_r) * APAD + kc * 16 + k_c) * 2;
                uint32_t kh4[4], kl4[4];
                ldsm4(kh4, Khb + off);
                ldsm4(kl4, Klb + off);
                #pragma unroll
                for (int mt = 0; mt < 2; mt++) {
                    mma16816(S[mt][2*p],     aQh[mt][kc], &kh4[0]);
                    mma16816(S[mt][2*p],     aQh[mt][kc], &kl4[0]);
                    mma16816(S[mt][2*p],     aQl[mt][kc], &kh4[0]);
                    mma16816(S[mt][2*p + 1], aQh[mt][kc], &kh4[2]);
                    mma16816(S[mt][2*p + 1], aQh[mt][kc], &kl4[2]);
                    mma16816(S[mt][2*p + 1], aQl[mt][kc], &kh4[2]);
                }
            }
        }

        #pragma unroll
        for (int mt = 0; mt < 2; mt++) {
            const int qr = qrow0 + mt * 16;
            float rm0 = -INFINITY, rm1 = -INFINITY;
            #pragma unroll
            for (int nt = 0; nt < 8; nt++) {
                const int kcol = k0 + nt * 8 + qt * 2;
                float* Sv = S[mt][nt];
                Sv[0] *= 0.125f * dtab[abs(qr - kcol)];
                Sv[1] *= 0.125f * dtab[abs(qr - kcol - 1)];
                Sv[2] *= 0.125f * dtab[abs(qr + 8 - kcol)];
                Sv[3] *= 0.125f * dtab[abs(qr + 8 - kcol - 1)];
                rm0 = fmaxf(rm0, fmaxf(Sv[0], Sv[1]));
                rm1 = fmaxf(rm1, fmaxf(Sv[2], Sv[3]));
            }
            rm0 = fmaxf(rm0, __shfl_xor_sync(0xffffffffu, rm0, 1));
            rm0 = fmaxf(rm0, __shfl_xor_sync(0xffffffffu, rm0, 2));
            rm1 = fmaxf(rm1, __shfl_xor_sync(0xffffffffu, rm1, 1));
            rm1 = fmaxf(rm1, __shfl_xor_sync(0xffffffffu, rm1, 2));

            const float mn0 = fmaxf(m_i[2*mt],     rm0);
            const float mn1 = fmaxf(m_i[2*mt + 1], rm1);
            const float sc0 = __expf(m_i[2*mt]     - mn0);
            const float sc1 = __expf(m_i[2*mt + 1] - mn1);

            float rs0 = 0.f, rs1 = 0.f;
            #pragma unroll
            for (int nt = 0; nt < 8; nt++) {
                float* Sv = S[mt][nt];
                Sv[0] = __expf(Sv[0] - mn0);
                Sv[1] = __expf(Sv[1] - mn0);
                Sv[2] = __expf(Sv[2] - mn1);
                Sv[3] = __expf(Sv[3] - mn1);
                rs0 += Sv[0] + Sv[1];
                rs1 += Sv[2] + Sv[3];
            }
            rs0 += __shfl_xor_sync(0xffffffffu, rs0, 1);
            rs0 += __shfl_xor_sync(0xffffffffu, rs0, 2);
            rs1 += __shfl_xor_sync(0xffffffffu, rs1, 1);
            rs1 += __shfl_xor_sync(0xffffffffu, rs1, 2);

            l_i[2*mt]     = l_i[2*mt]     * sc0 + rs0;
            l_i[2*mt + 1] = l_i[2*mt + 1] * sc1 + rs1;
            m_i[2*mt]     = mn0;
            m_i[2*mt + 1] = mn1;

            #pragma unroll
            for (int nt = 0; nt < 8; nt++) {
                O[mt][nt][0] *= sc0; O[mt][nt][1] *= sc0;
                O[mt][nt][2] *= sc1; O[mt][nt][3] *= sc1;
            }
        }

        #pragma unroll
        for (int j = 0; j < 4; j++) {
            uint32_t aPh2[2][4], aPl2[2][4];
            #pragma unroll
            for (int mt = 0; mt < 2; mt++) {
                const float* s0 = S[mt][2 * j];
                const float* s1 = S[mt][2 * j + 1];
                aPh2[mt][0] = pack_bf16(s0[0], s0[1]);
                aPh2[mt][1] = pack_bf16(s0[2], s0[3]);
                aPh2[mt][2] = pack_bf16(s1[0], s1[1]);
                aPh2[mt][3] = pack_bf16(s1[2], s1[3]);
                __nv_bfloat162 h0 = *(__nv_bfloat162*)&aPh2[mt][0];
                __nv_bfloat162 h1 = *(__nv_bfloat162*)&aPh2[mt][1];
                __nv_bfloat162 h2 = *(__nv_bfloat162*)&aPh2[mt][2];
                __nv_bfloat162 h3 = *(__nv_bfloat162*)&aPh2[mt][3];
                aPl2[mt][0] = pack_bf16(s0[0] - __bfloat162float(h0.x),
                                        s0[1] - __bfloat162float(h0.y));
                aPl2[mt][1] = pack_bf16(s0[2] - __bfloat162float(h1.x),
                                        s0[3] - __bfloat162float(h1.y));
                aPl2[mt][2] = pack_bf16(s1[0] - __bfloat162float(h2.x),
                                        s1[1] - __bfloat162float(h2.y));
                aPl2[mt][3] = pack_bf16(s1[2] - __bfloat162float(h3.x),
                                        s1[3] - __bfloat162float(h3.y));
            }
            #pragma unroll
            for (int db = 0; db < 4; db++) {
                const uint32_t off =
                    (uint32_t)((j * 16 + t_loc) * APAD + db * 16 + d_grp) * 2;
                uint32_t vh[4], vl[4];
                ldsm4t(vh, vhb + off);
                ldsm4t(vl, vlb + off);
                #pragma unroll
                for (int mt = 0; mt < 2; mt++) {
                    mma16816(O[mt][2 * db],     aPh2[mt], &vh[0]);
                    mma16816(O[mt][2 * db],     aPh2[mt], &vl[0]);
                    mma16816(O[mt][2 * db],     aPl2[mt], &vh[0]);
                    mma16816(O[mt][2 * db + 1], aPh2[mt], &vh[2]);
                    mma16816(O[mt][2 * db + 1], aPh2[mt], &vl[2]);
                    mma16816(O[mt][2 * db + 1], aPl2[mt], &vh[2]);
                }
            }
        }
        s ^= 1;
    }

    // ---- far-field contribution + epilogue ----
    #pragma unroll
    for (int mt = 0; mt < 2; mt++) {
        const float eh0 = __expf(-m_i[2*mt]);
        const float eh1 = __expf(-m_i[2*mt + 1]);
        const float lf0 = l_i[2*mt]     + eh0 * (float)nfar;
        const float lf1 = l_i[2*mt + 1] + eh1 * (float)nfar;
        const float inv0 = 1.0f / lf0;
        const float inv1 = 1.0f / lf1;
        const size_t r0 = rowbase + qrow0 + mt * 16;
        #pragma unroll
        for (int nt = 0; nt < 8; nt++) {
            const int dcol = nt * 8 + qt * 2;
            const float f0 = farV[dcol], f1 = farV[dcol + 1];
            const int col = h * D_ + dcol;
            const float v0 = (O[mt][nt][0] + eh0 * f0) * inv0;
            const float v1 = (O[mt][nt][1] + eh0 * f1) * inv0;
            const float v2 = (O[mt][nt][2] + eh1 * f0) * inv1;
            const float v3 = (O[mt][nt][3] + eh1 * f1) * inv1;
            uint32_t h0 = pack_bf16(v0, v1);
            uint32_t h1 = pack_bf16(v2, v3);
            __nv_bfloat162 H0 = *(__nv_bfloat162*)&h0;
            __nv_bfloat162 H1 = *(__nv_bfloat162*)&h1;
            uint32_t l0 = pack_bf16(v0 - __bfloat162float(H0.x),
                                    v1 - __bfloat162float(H0.y));
            uint32_t l1 = pack_bf16(v2 - __bfloat162float(H1.x),
                                    v3 - __bfloat162float(H1.y));
            *(uint32_t*)&outh[r0 * E_ + col]       = h0;
            *(uint32_t*)&outl[r0 * E_ + col]       = l0;
            *(uint32_t*)&outh[(r0 + 8) * E_ + col] = h1;
            *(uint32_t*)&outl[(r0 + 8) * E_ + col] = l1;
        }
    }
}

// ===========================================================================
extern "C" void kernel_launch(void* const* d_in, const int* in_sizes, int n_in,
                              void* d_out, int out_size)
{
    const float* x      = (const float*)d_in[0];
    const float* Wqkv_w = (const float*)d_in[1];
    const float* Wqkv_b = (const float*)d_in[2];
    const float* out_w  = (const float*)d_in[3];
    const float* out_b  = (const float*)d_in[4];
    const float* dd     = (const float*)d_in[5];
    float* out = (float*)d_out;

    __nv_bfloat16 *xh, *xl, *wqh, *wql, *owh, *owl, *qkvh, *qkvl, *ath, *atl;
    cudaGetSymbolAddress((void**)&xh,  g_xh);  cudaGetSymbolAddress((void**)&xl,  g_xl);
    cudaGetSymbolAddress((void**)&wqh, g_wqh); cudaGetSymbolAddress((void**)&wql, g_wql);
    cudaGetSymbolAddress((void**)&owh, g_owh); cudaGetSymbolAddress((void**)&owl, g_owl);
    cudaGetSymbolAddress((void**)&qkvh, g_qkvh); cudaGetSymbolAddress((void**)&qkvl, g_qkvl);
    cudaGetSymbolAddress((void**)&ath, g_ath); cudaGetSymbolAddress((void**)&atl, g_atl);

    cudaFuncSetAttribute(gemm_tc, cudaFuncAttributeMaxDynamicSharedMemorySize,
                         GEMM_SMEM);
    cudaFuncSetAttribute(attn_tc, cudaFuncAttributeMaxDynamicSharedMemorySize,
                         ATTN_SMEM);

    // 0. split inputs/weights to bf16 hi/lo
    split_bf16<<<(M_ * E_ / 4 + 255) / 256, 256>>>(x, xh, xl, M_ * E_ / 4);
    split_bf16<<<(E3_ * E_ / 4 + 255) / 256, 256>>>(Wqkv_w, wqh, wql, E3_ * E_ / 4);
    split_bf16<<<(E_ * E_ / 4 + 255) / 256, 256>>>(out_w, owh, owl, E_ * E_ / 4);

    // 1. QKV projection -> split bf16 qkv
    gemm_tc<<<dim3(E3_ / 128, M_ / 128), 128, GEMM_SMEM>>>(
        xh, xl, wqh, wql, Wqkv_b, nullptr, qkvh, qkvl, M_, E3_, E_);

    // 1b. per-tile V column sums (for far-field)
    vtile_sum<<<dim3(NT_, H_, B_), 64>>>(qkvh, qkvl);

    // 2. banded attention -> split bf16 attn out (q-tile 256)
    attn_tc<<<dim3(S_ / 256, H_, B_), 256, ATTN_SMEM>>>(qkvh, qkvl, dd, ath, atl);

    // 3. output projection -> fp32 out
    gemm_tc<<<dim3(E_ / 128, M_ / 128), 128, GEMM_SMEM>>>(
        ath, atl, owh, owl, out_b, out, nullptr, nullptr, M_, E_, E_);
}